// round 1
// baseline (speedup 1.0000x reference)
#include <cuda_runtime.h>

#define N_NODES 100000
#define EDGES   640000
#define DIM     128
#define DIM2    256
#define LAYERS  5
#define BN_EPS  1e-5f
#define TM      64   // GEMM M tile

// ---------------- scratch (static device allocations; no cudaMalloc) ----------
__device__ float g_agg[(size_t)N_NODES * DIM];    // 51.2 MB
__device__ float g_z[(size_t)N_NODES * DIM2];     // 102.4 MB
__device__ int   g_rowptr[N_NODES + 1];
__device__ int   g_cnt[N_NODES];
__device__ int   g_cursor[N_NODES];
__device__ int   g_srcs[EDGES];

// ---------------- packed f32x2 helpers ----------------------------------------
__device__ __forceinline__ unsigned long long pack2(float x, float y) {
    unsigned long long r;
    asm("mov.b64 %0, {%1, %2};" : "=l"(r) : "f"(x), "f"(y));
    return r;
}
__device__ __forceinline__ void fma2(unsigned long long& d,
                                     unsigned long long a, unsigned long long b) {
    asm("fma.rn.f32x2 %0, %1, %2, %0;" : "+l"(d) : "l"(a), "l"(b));
}
__device__ __forceinline__ float2 unpack2(unsigned long long p) {
    float2 f;
    asm("mov.b64 {%0, %1}, %2;" : "=f"(f.x), "=f"(f.y) : "l"(p));
    return f;
}

// ---------------- CSR build ----------------------------------------------------
__global__ void k_zero() {
    int i = blockIdx.x * blockDim.x + threadIdx.x;
    if (i < N_NODES) { g_cnt[i] = 0; g_cursor[i] = 0; }
}

__global__ void k_hist(const int* __restrict__ dst) {
    int e = blockIdx.x * blockDim.x + threadIdx.x;
    if (e < EDGES) atomicAdd(&g_cnt[dst[e]], 1);
}

__global__ void k_scan() {
    __shared__ int part[1024];
    int t = threadIdx.x;
    const int chunk = (N_NODES + 1023) / 1024;
    int s0 = t * chunk;
    int s1 = min(s0 + chunk, N_NODES);
    int s = 0;
    for (int i = s0; i < s1; i++) s += g_cnt[i];
    part[t] = s;
    __syncthreads();
    for (int off = 1; off < 1024; off <<= 1) {
        int v = (t >= off) ? part[t - off] : 0;
        __syncthreads();
        part[t] += v;
        __syncthreads();
    }
    int pre = (t == 0) ? 0 : part[t - 1];
    for (int i = s0; i < s1; i++) { g_rowptr[i] = pre; pre += g_cnt[i]; }
    if (t == 1023) g_rowptr[N_NODES] = pre;
}

__global__ void k_fill(const int* __restrict__ src, const int* __restrict__ dst) {
    int e = blockIdx.x * blockDim.x + threadIdx.x;
    if (e < EDGES) {
        int d = dst[e];
        int p = g_rowptr[d] + atomicAdd(&g_cursor[d], 1);
        g_srcs[p] = src[e];
    }
}

// ---------------- aggregation: agg[i] = h[i] + sum_{j->i} h[j] ------------------
__global__ void k_aggregate(const float* __restrict__ h) {
    int gw = (blockIdx.x * blockDim.x + threadIdx.x) >> 5;
    int lane = threadIdx.x & 31;
    if (gw >= N_NODES) return;
    const float4* hv = (const float4*)h;
    float4 acc = __ldg(&hv[(size_t)gw * 32 + lane]);
    int e0 = g_rowptr[gw], e1 = g_rowptr[gw + 1];
    for (int e = e0; e < e1; e++) {
        int j = g_srcs[e];
        float4 v = __ldg(&hv[(size_t)j * 32 + lane]);
        acc.x += v.x; acc.y += v.y; acc.z += v.z; acc.w += v.w;
    }
    ((float4*)g_agg)[(size_t)gw * 32 + lane] = acc;
}

// ---------------- GEMM1: z = relu(BN1(agg @ W1 + b1))  [N,128]x[128,256] --------
// persistent blocks, W resident in smem, f32x2 packed FMA.
__global__ void __launch_bounds__(256, 1) k_gemm1(
    const float* __restrict__ W,     // [128,256] row-major
    const float* __restrict__ bias,  // [256]
    const float* __restrict__ bn_g, const float* __restrict__ bn_b,
    const float* __restrict__ bn_m, const float* __restrict__ bn_v)
{
    extern __shared__ float smem[];
    float* sW = smem;                 // 128*256 floats
    float* sA = smem + 128 * 256;     // 64*128 floats
    int tid = threadIdx.x;
    int tx = tid & 31, ty = tid >> 5;

    // load full W into smem (8192 float4)
    {
        const float4* s = (const float4*)W;
        float4* d = (float4*)sW;
        #pragma unroll
        for (int i = 0; i < 32; i++) d[i * 256 + tid] = s[i * 256 + tid];
    }

    // per-thread column pairs: cols = jp*64 + tx*2 + {0,1}
    float2 al[4], be[4];
    #pragma unroll
    for (int jp = 0; jp < 4; jp++) {
        int c = jp * 64 + tx * 2;
        float s0 = bn_g[c]     * rsqrtf(bn_v[c]     + BN_EPS);
        float s1 = bn_g[c + 1] * rsqrtf(bn_v[c + 1] + BN_EPS);
        al[jp] = make_float2(s0, s1);
        be[jp] = make_float2((bias[c]     - bn_m[c])     * s0 + bn_b[c],
                             (bias[c + 1] - bn_m[c + 1]) * s1 + bn_b[c + 1]);
    }
    __syncthreads();

    int ntiles = (N_NODES + TM - 1) / TM;
    for (int tile = blockIdx.x; tile < ntiles; tile += gridDim.x) {
        int row0 = tile * TM;
        // load A tile 64x128 (2048 float4, 8 per thread), zero-fill tail rows
        #pragma unroll
        for (int q = 0; q < 8; q++) {
            int f = q * 256 + tid;
            int r = f >> 5;
            int k4 = f & 31;
            float4 v = make_float4(0.f, 0.f, 0.f, 0.f);
            if (row0 + r < N_NODES) v = ((const float4*)g_agg)[(size_t)(row0 + r) * 32 + k4];
            ((float4*)sA)[f] = v;
        }
        __syncthreads();

        unsigned long long acc[8][4];
        #pragma unroll
        for (int i = 0; i < 8; i++)
            #pragma unroll
            for (int j = 0; j < 4; j++) acc[i][j] = 0ull;

        #pragma unroll 2
        for (int k = 0; k < 128; k += 4) {
            float4 a4[8];
            #pragma unroll
            for (int i = 0; i < 8; i++)
                a4[i] = *(const float4*)&sA[(ty * 8 + i) * 128 + k];
            #pragma unroll
            for (int kk = 0; kk < 4; kk++) {
                unsigned long long b2[4];
                #pragma unroll
                for (int jp = 0; jp < 4; jp++)
                    b2[jp] = *(const unsigned long long*)&sW[(k + kk) * 256 + jp * 64 + tx * 2];
                #pragma unroll
                for (int i = 0; i < 8; i++) {
                    float a = (kk == 0) ? a4[i].x : (kk == 1) ? a4[i].y
                            : (kk == 2) ? a4[i].z : a4[i].w;
                    unsigned long long ap = pack2(a, a);
                    #pragma unroll
                    for (int jp = 0; jp < 4; jp++) fma2(acc[i][jp], ap, b2[jp]);
                }
            }
        }

        #pragma unroll
        for (int i = 0; i < 8; i++) {
            int r = row0 + ty * 8 + i;
            if (r < N_NODES) {
                #pragma unroll
                for (int jp = 0; jp < 4; jp++) {
                    float2 y = unpack2(acc[i][jp]);
                    float2 o;
                    o.x = fmaxf(fmaf(y.x, al[jp].x, be[jp].x), 0.f);
                    o.y = fmaxf(fmaf(y.y, al[jp].y, be[jp].y), 0.f);
                    *(float2*)&g_z[(size_t)r * 256 + jp * 64 + tx * 2] = o;
                }
            }
        }
        __syncthreads();
    }
}

// ---------------- GEMM2: h = BN_o(z @ W2 + b2) (+relu)  [N,256]x[256,128] -------
__global__ void __launch_bounds__(256, 1) k_gemm2(
    const float* __restrict__ W,     // [256,128] row-major
    const float* __restrict__ bias,  // [128]
    const float* __restrict__ bn_g, const float* __restrict__ bn_b,
    const float* __restrict__ bn_m, const float* __restrict__ bn_v,
    float* __restrict__ out, int do_relu)
{
    extern __shared__ float smem[];
    float* sW = smem;                 // 256*128 floats
    float* sA = smem + 256 * 128;     // 64*256 floats
    int tid = threadIdx.x;
    int tx = tid & 31, ty = tid >> 5;

    {
        const float4* s = (const float4*)W;
        float4* d = (float4*)sW;
        #pragma unroll
        for (int i = 0; i < 32; i++) d[i * 256 + tid] = s[i * 256 + tid];
    }

    float2 al[2], be[2];
    #pragma unroll
    for (int jp = 0; jp < 2; jp++) {
        int c = jp * 64 + tx * 2;
        float s0 = bn_g[c]     * rsqrtf(bn_v[c]     + BN_EPS);
        float s1 = bn_g[c + 1] * rsqrtf(bn_v[c + 1] + BN_EPS);
        al[jp] = make_float2(s0, s1);
        be[jp] = make_float2((bias[c]     - bn_m[c])     * s0 + bn_b[c],
                             (bias[c + 1] - bn_m[c + 1]) * s1 + bn_b[c + 1]);
    }
    __syncthreads();

    int ntiles = (N_NODES + TM - 1) / TM;
    for (int tile = blockIdx.x; tile < ntiles; tile += gridDim.x) {
        int row0 = tile * TM;
        // load A tile 64x256 (4096 float4, 16 per thread)
        #pragma unroll
        for (int q = 0; q < 16; q++) {
            int f = q * 256 + tid;
            int r = f >> 6;
            int k4 = f & 63;
            float4 v = make_float4(0.f, 0.f, 0.f, 0.f);
            if (row0 + r < N_NODES) v = ((const float4*)g_z)[(size_t)(row0 + r) * 64 + k4];
            ((float4*)sA)[f] = v;
        }
        __syncthreads();

        unsigned long long acc[8][2];
        #pragma unroll
        for (int i = 0; i < 8; i++) { acc[i][0] = 0ull; acc[i][1] = 0ull; }

        #pragma unroll 2
        for (int k = 0; k < 256; k += 4) {
            float4 a4[8];
            #pragma unroll
            for (int i = 0; i < 8; i++)
                a4[i] = *(const float4*)&sA[(ty * 8 + i) * 256 + k];
            #pragma unroll
            for (int kk = 0; kk < 4; kk++) {
                unsigned long long b2[2];
                #pragma unroll
                for (int jp = 0; jp < 2; jp++)
                    b2[jp] = *(const unsigned long long*)&sW[(k + kk) * 128 + jp * 64 + tx * 2];
                #pragma unroll
                for (int i = 0; i < 8; i++) {
                    float a = (kk == 0) ? a4[i].x : (kk == 1) ? a4[i].y
                            : (kk == 2) ? a4[i].z : a4[i].w;
                    unsigned long long ap = pack2(a, a);
                    fma2(acc[i][0], ap, b2[0]);
                    fma2(acc[i][1], ap, b2[1]);
                }
            }
        }

        #pragma unroll
        for (int i = 0; i < 8; i++) {
            int r = row0 + ty * 8 + i;
            if (r < N_NODES) {
                #pragma unroll
                for (int jp = 0; jp < 2; jp++) {
                    float2 y = unpack2(acc[i][jp]);
                    float2 o;
                    o.x = fmaf(y.x, al[jp].x, be[jp].x);
                    o.y = fmaf(y.y, al[jp].y, be[jp].y);
                    if (do_relu) { o.x = fmaxf(o.x, 0.f); o.y = fmaxf(o.y, 0.f); }
                    *(float2*)&out[(size_t)r * 128 + jp * 64 + tx * 2] = o;
                }
            }
        }
        __syncthreads();
    }
}

// ---------------- launch --------------------------------------------------------
extern "C" void kernel_launch(void* const* d_in, const int* in_sizes, int n_in,
                              void* d_out, int out_size) {
    const float* x     = (const float*)d_in[0];
    const int*   ei    = (const int*)d_in[1];
    const float* W1    = (const float*)d_in[2];
    const float* b1    = (const float*)d_in[3];
    const float* bn1_g = (const float*)d_in[4];
    const float* bn1_b = (const float*)d_in[5];
    const float* bn1_m = (const float*)d_in[6];
    const float* bn1_v = (const float*)d_in[7];
    const float* W2    = (const float*)d_in[8];
    const float* b2    = (const float*)d_in[9];
    const float* bno_g = (const float*)d_in[10];
    const float* bno_b = (const float*)d_in[11];
    const float* bno_m = (const float*)d_in[12];
    const float* bno_v = (const float*)d_in[13];
    float* out = (float*)d_out;

    const size_t SMEM1 = (128 * 256 + 64 * 128) * sizeof(float);   // 160 KB
    const size_t SMEM2 = (256 * 128 + 64 * 256) * sizeof(float);   // 192 KB
    cudaFuncSetAttribute(k_gemm1, cudaFuncAttributeMaxDynamicSharedMemorySize, (int)SMEM1);
    cudaFuncSetAttribute(k_gemm2, cudaFuncAttributeMaxDynamicSharedMemorySize, (int)SMEM2);

    const int* src = ei;
    const int* dst = ei + EDGES;

    // CSR build (once per launch; reused across 5 layers)
    k_zero<<<(N_NODES + 255) / 256, 256>>>();
    k_hist<<<(EDGES + 255) / 256, 256>>>(dst);
    k_scan<<<1, 1024>>>();
    k_fill<<<(EDGES + 255) / 256, 256>>>(src, dst);

    const float* h = x;
    for (int l = 0; l < LAYERS; l++) {
        k_aggregate<<<(N_NODES * 32 + 255) / 256, 256>>>(h);
        k_gemm1<<<148, 256, SMEM1>>>(W1 + (size_t)l * 128 * 256,
                                     b1 + (size_t)l * 256,
                                     bn1_g + (size_t)l * 256, bn1_b + (size_t)l * 256,
                                     bn1_m + (size_t)l * 256, bn1_v + (size_t)l * 256);
        k_gemm2<<<148, 256, SMEM2>>>(W2 + (size_t)l * 256 * 128,
                                     b2 + (size_t)l * 128,
                                     bno_g + (size_t)l * 128, bno_b + (size_t)l * 128,
                                     bno_m + (size_t)l * 128, bno_v + (size_t)l * 128,
                                     out, (l != LAYERS - 1) ? 1 : 0);
        h = out;
    }
}

// round 3
// speedup vs baseline: 1.4525x; 1.4525x over previous
#include <cuda_runtime.h>
#include <cuda_bf16.h>
#include <cstdint>

#define N_NODES 100000
#define EDGES   640000
#define LAYERS  5
#define BN_EPS  1e-5f
#define NT      782          // ceil(100000/128)
#define GRID_G  148

// ---------------- static scratch ------------------------------------------------
__device__ __nv_bfloat16 g_a_hi[(size_t)N_NODES * 128];
__device__ __nv_bfloat16 g_a_lo[(size_t)N_NODES * 128];
__device__ __nv_bfloat16 g_z_hi[(size_t)N_NODES * 256];
__device__ __nv_bfloat16 g_z_lo[(size_t)N_NODES * 256];
__device__ __nv_bfloat16 g_w1t[LAYERS * 2 * 32768];   // Wt1: [l][term][n=256][k=128]
__device__ __nv_bfloat16 g_w2t[LAYERS * 2 * 32768];   // Wt2: [l][term][n=128][k=256]
__device__ int g_rowptr[N_NODES + 1];
__device__ int g_cnt[N_NODES];
__device__ int g_cursor[N_NODES];
__device__ int g_srcs[EDGES];

// ---------------- helpers -------------------------------------------------------
__device__ __forceinline__ uint32_t smem_u32(const void* p) {
    uint32_t a;
    asm("{ .reg .u64 t; cvta.to.shared.u64 t, %1; cvt.u32.u64 %0, t; }" : "=r"(a) : "l"(p));
    return a;
}
__device__ __forceinline__ uint32_t pack_bf(__nv_bfloat16 a, __nv_bfloat16 b) {
    return ((uint32_t)__bfloat16_as_ushort(b) << 16) | (uint32_t)__bfloat16_as_ushort(a);
}
__device__ __forceinline__ void split_bf(float x, __nv_bfloat16& h, __nv_bfloat16& l) {
    h = __float2bfloat16(x);
    l = __float2bfloat16(x - __bfloat162float(h));
}

#define LDSM_X4(r0, r1, r2, r3, addr) \
    asm volatile("ldmatrix.sync.aligned.m8n8.x4.shared.b16 {%0,%1,%2,%3}, [%4];" \
        : "=r"(r0), "=r"(r1), "=r"(r2), "=r"(r3) : "r"(addr))

__device__ __forceinline__ void mma_bf16(float& c0, float& c1, float& c2, float& c3,
        uint32_t a0, uint32_t a1, uint32_t a2, uint32_t a3, uint32_t b0, uint32_t b1) {
    asm volatile("mma.sync.aligned.m16n8k16.row.col.f32.bf16.bf16.f32 "
        "{%0,%1,%2,%3}, {%4,%5,%6,%7}, {%8,%9}, {%0,%1,%2,%3};"
        : "+f"(c0), "+f"(c1), "+f"(c2), "+f"(c3)
        : "r"(a0), "r"(a1), "r"(a2), "r"(a3), "r"(b0), "r"(b1));
}

// ---------------- CSR build ------------------------------------------------------
__global__ void k_zero() {
    int i = blockIdx.x * blockDim.x + threadIdx.x;
    if (i < N_NODES) { g_cnt[i] = 0; g_cursor[i] = 0; }
}
__global__ void k_hist(const int* __restrict__ dst) {
    int e = blockIdx.x * blockDim.x + threadIdx.x;
    if (e < EDGES) atomicAdd(&g_cnt[dst[e]], 1);
}
__global__ void k_scan() {
    __shared__ int part[1024];
    int t = threadIdx.x;
    const int chunk = (N_NODES + 1023) / 1024;
    int s0 = t * chunk, s1 = min(s0 + chunk, N_NODES);
    int s = 0;
    for (int i = s0; i < s1; i++) s += g_cnt[i];
    part[t] = s;
    __syncthreads();
    for (int off = 1; off < 1024; off <<= 1) {
        int v = (t >= off) ? part[t - off] : 0;
        __syncthreads();
        part[t] += v;
        __syncthreads();
    }
    int pre = (t == 0) ? 0 : part[t - 1];
    for (int i = s0; i < s1; i++) { g_rowptr[i] = pre; pre += g_cnt[i]; }
    if (t == 1023) g_rowptr[N_NODES] = pre;
}
__global__ void k_fill(const int* __restrict__ src, const int* __restrict__ dst) {
    int e = blockIdx.x * blockDim.x + threadIdx.x;
    if (e < EDGES) {
        int d = dst[e];
        int p = g_rowptr[d] + atomicAdd(&g_cursor[d], 1);
        g_srcs[p] = src[e];
    }
}

// ---------------- W -> split-bf16 transposed images ------------------------------
__global__ void k_wconv(const float* __restrict__ W1, const float* __restrict__ W2) {
    int i = blockIdx.x * blockDim.x + threadIdx.x;
    const int TOT = LAYERS * 32768;
    if (i < TOT) {
        int l = i >> 15, r = i & 32767;
        int k = r >> 8, n = r & 255;           // W1[l][k][n]
        __nv_bfloat16 hi, lo;
        split_bf(W1[i], hi, lo);
        g_w1t[(size_t)l * 65536 + n * 128 + k] = hi;
        g_w1t[(size_t)l * 65536 + 32768 + n * 128 + k] = lo;
    } else if (i < 2 * TOT) {
        int j = i - TOT;
        int l = j >> 15, r = j & 32767;
        int k = r >> 7, n = r & 127;           // W2[l][k][n]
        __nv_bfloat16 hi, lo;
        split_bf(W2[j], hi, lo);
        g_w2t[(size_t)l * 65536 + n * 256 + k] = hi;
        g_w2t[(size_t)l * 65536 + 32768 + n * 256 + k] = lo;
    }
}

// ---------------- aggregation: agg = h_i + sum h_j -> split bf16 -----------------
__global__ void k_aggregate(const float* __restrict__ h) {
    int gw = (blockIdx.x * blockDim.x + threadIdx.x) >> 5;
    int lane = threadIdx.x & 31;
    if (gw >= N_NODES) return;
    const float4* hv = (const float4*)h;
    float4 acc = __ldg(&hv[(size_t)gw * 32 + lane]);
    int e0 = g_rowptr[gw], e1 = g_rowptr[gw + 1];
    for (int e = e0; e < e1; e++) {
        int j = g_srcs[e];
        float4 v = __ldg(&hv[(size_t)j * 32 + lane]);
        acc.x += v.x; acc.y += v.y; acc.z += v.z; acc.w += v.w;
    }
    __nv_bfloat16 h0, h1, h2, h3, l0, l1, l2, l3;
    split_bf(acc.x, h0, l0); split_bf(acc.y, h1, l1);
    split_bf(acc.z, h2, l2); split_bf(acc.w, h3, l3);
    uint2 ph, pl;
    ph.x = pack_bf(h0, h1); ph.y = pack_bf(h2, h3);
    pl.x = pack_bf(l0, l1); pl.y = pack_bf(l2, l3);
    ((uint2*)g_a_hi)[(size_t)gw * 32 + lane] = ph;
    ((uint2*)g_a_lo)[(size_t)gw * 32 + lane] = pl;
}

// ---------------- SMEM layouts ----------------------------------------------------
// GEMM1 (row stride 272B for k=128+pad):
#define STR1B    272
#define G1_WH    0
#define G1_WL    69632
#define G1_AH    139264
#define G1_AL    174080
#define G1_ALPHA 208896
#define G1_BETA  209920
#define SMEM1    210944
// GEMM2 (W rows: k=256 -> 528B; Z chunk rows: 272B):
#define STR2B    528
#define G2_WH    0
#define G2_WL    67584
#define G2_ZH    135168
#define G2_ZL    169984
#define G2_ALPHA 204800
#define G2_BETA  205312
#define SMEM2    205824

// ---------------- GEMM1: z = relu(BN1(agg @ W1 + b1)),  [N,128]x[128,256] --------
__global__ void __launch_bounds__(256, 1) k_gemm1(
    int layer, const float* __restrict__ bias,
    const float* __restrict__ bn_g, const float* __restrict__ bn_b,
    const float* __restrict__ bn_m, const float* __restrict__ bn_v)
{
    extern __shared__ char sm[];
    uint32_t sb = smem_u32(sm);
    int tid = threadIdx.x, lane = tid & 31, wid = tid >> 5;

    // W (hi+lo) into padded smem [n=256][k=128]
    {
        const uint4* s = (const uint4*)(g_w1t + (size_t)layer * 65536);
        #pragma unroll 4
        for (int i = tid; i < 4096; i += 256) {
            int r = i >> 4, c = i & 15;
            *(uint4*)(sm + G1_WH + r * STR1B + c * 16) = s[i];
            *(uint4*)(sm + G1_WL + r * STR1B + c * 16) = s[i + 4096];
        }
    }
    float* sAl = (float*)(sm + G1_ALPHA);
    float* sBe = (float*)(sm + G1_BETA);
    if (tid < 256) {
        int c = tid;
        float s = bn_g[c] * rsqrtf(bn_v[c] + BN_EPS);
        sAl[c] = s;
        sBe[c] = (bias[c] - bn_m[c]) * s + bn_b[c];
    }

    int m0 = (wid >> 2) * 64, n0 = (wid & 3) * 64;
    // ldmatrix lane addresses
    uint32_t aoff = (uint32_t)((m0 + (lane & 15)) * STR1B + ((lane >> 4) << 4));
    uint32_t aAH = sb + G1_AH + aoff;
    uint32_t aAL = sb + G1_AL + aoff;
    uint32_t boff = (uint32_t)((n0 + ((lane >> 4) << 3) + (lane & 7)) * STR1B + (((lane >> 3) & 1) << 4));
    uint32_t aWH = sb + G1_WH + boff;
    uint32_t aWL = sb + G1_WL + boff;

    const uint4* ah = (const uint4*)g_a_hi;
    const uint4* al = (const uint4*)g_a_lo;

    for (int tile = blockIdx.x; tile < NT; tile += gridDim.x) {
        int row0 = tile << 7;
        int rv = min(128, N_NODES - row0);
        __syncthreads();
        #pragma unroll 4
        for (int i = tid; i < 2048; i += 256) {
            int r = i >> 4, c = i & 15;
            uint4 vh = make_uint4(0, 0, 0, 0), vl = vh;
            if (r < rv) {
                size_t si = (size_t)(row0 + r) * 16 + c;
                vh = ah[si]; vl = al[si];
            }
            *(uint4*)(sm + G1_AH + r * STR1B + c * 16) = vh;
            *(uint4*)(sm + G1_AL + r * STR1B + c * 16) = vl;
        }
        __syncthreads();

        float acc[4][8][4];
        #pragma unroll
        for (int i = 0; i < 4; i++)
            #pragma unroll
            for (int j = 0; j < 8; j++)
                #pragma unroll
                for (int f = 0; f < 4; f++) acc[i][j][f] = 0.f;

        #pragma unroll 2
        for (int ks = 0; ks < 8; ks++) {
            uint32_t kb = ks << 5;
            uint32_t Ah[4][4], Alr[4][4], B[4][4];
            #pragma unroll
            for (int i = 0; i < 4; i++) {
                LDSM_X4(Ah[i][0], Ah[i][1], Ah[i][2], Ah[i][3], aAH + i * (16 * STR1B) + kb);
                LDSM_X4(Alr[i][0], Alr[i][1], Alr[i][2], Alr[i][3], aAL + i * (16 * STR1B) + kb);
            }
            #pragma unroll
            for (int j2 = 0; j2 < 4; j2++)
                LDSM_X4(B[j2][0], B[j2][1], B[j2][2], B[j2][3], aWH + j2 * (16 * STR1B) + kb);
            #pragma unroll
            for (int i = 0; i < 4; i++)
                #pragma unroll
                for (int j = 0; j < 8; j++)
                    mma_bf16(acc[i][j][0], acc[i][j][1], acc[i][j][2], acc[i][j][3],
                             Ah[i][0], Ah[i][1], Ah[i][2], Ah[i][3],
                             B[j >> 1][(j & 1) * 2], B[j >> 1][(j & 1) * 2 + 1]);
            #pragma unroll
            for (int i = 0; i < 4; i++)
                #pragma unroll
                for (int j = 0; j < 8; j++)
                    mma_bf16(acc[i][j][0], acc[i][j][1], acc[i][j][2], acc[i][j][3],
                             Alr[i][0], Alr[i][1], Alr[i][2], Alr[i][3],
                             B[j >> 1][(j & 1) * 2], B[j >> 1][(j & 1) * 2 + 1]);
            #pragma unroll
            for (int j2 = 0; j2 < 4; j2++)
                LDSM_X4(B[j2][0], B[j2][1], B[j2][2], B[j2][3], aWL + j2 * (16 * STR1B) + kb);
            #pragma unroll
            for (int i = 0; i < 4; i++)
                #pragma unroll
                for (int j = 0; j < 8; j++)
                    mma_bf16(acc[i][j][0], acc[i][j][1], acc[i][j][2], acc[i][j][3],
                             Ah[i][0], Ah[i][1], Ah[i][2], Ah[i][3],
                             B[j >> 1][(j & 1) * 2], B[j >> 1][(j & 1) * 2 + 1]);
        }

        // epilogue: BN + relu + split-bf16 store
        int q = lane & 3;
        uint32_t* zh = (uint32_t*)g_z_hi;
        uint32_t* zl = (uint32_t*)g_z_lo;
        #pragma unroll
        for (int i = 0; i < 4; i++) {
            #pragma unroll
            for (int hf = 0; hf < 2; hf++) {
                int r = row0 + m0 + i * 16 + (lane >> 2) + hf * 8;
                if (r < N_NODES) {
                    size_t rb = (size_t)r * 128 + (n0 >> 1) + q;
                    #pragma unroll
                    for (int j = 0; j < 8; j++) {
                        int c = n0 + j * 8 + 2 * q;
                        float z0 = fmaxf(fmaf(acc[i][j][hf * 2],     sAl[c],     sBe[c]),     0.f);
                        float z1 = fmaxf(fmaf(acc[i][j][hf * 2 + 1], sAl[c + 1], sBe[c + 1]), 0.f);
                        __nv_bfloat16 h0, h1, l0, l1;
                        split_bf(z0, h0, l0); split_bf(z1, h1, l1);
                        zh[rb + j * 4] = pack_bf(h0, h1);
                        zl[rb + j * 4] = pack_bf(l0, l1);
                    }
                }
            }
        }
    }
}

// ---------------- GEMM2: h = BN_o(z @ W2 + b2)(+relu),  [N,256]x[256,128] --------
__global__ void __launch_bounds__(256, 1) k_gemm2(
    int layer, const float* __restrict__ bias,
    const float* __restrict__ bn_g, const float* __restrict__ bn_b,
    const float* __restrict__ bn_m, const float* __restrict__ bn_v,
    float* __restrict__ out, int relu)
{
    extern __shared__ char sm[];
    uint32_t sb = smem_u32(sm);
    int tid = threadIdx.x, lane = tid & 31, wid = tid >> 5;

    // W2t (hi+lo) into padded smem [n=128][k=256]
    {
        const uint4* s = (const uint4*)(g_w2t + (size_t)layer * 65536);
        #pragma unroll 4
        for (int i = tid; i < 4096; i += 256) {
            int r = i >> 5, c = i & 31;
            *(uint4*)(sm + G2_WH + r * STR2B + c * 16) = s[i];
            *(uint4*)(sm + G2_WL + r * STR2B + c * 16) = s[i + 4096];
        }
    }
    float* sAl = (float*)(sm + G2_ALPHA);
    float* sBe = (float*)(sm + G2_BETA);
    if (tid < 128) {
        int c = tid;
        float s = bn_g[c] * rsqrtf(bn_v[c] + BN_EPS);
        sAl[c] = s;
        sBe[c] = (bias[c] - bn_m[c]) * s + bn_b[c];
    }

    int m0 = (wid >> 2) * 64, n0 = (wid & 3) * 32;
    uint32_t aoff = (uint32_t)((m0 + (lane & 15)) * STR1B + ((lane >> 4) << 4));
    uint32_t aZH = sb + G2_ZH + aoff;
    uint32_t aZL = sb + G2_ZL + aoff;
    uint32_t boff = (uint32_t)((n0 + ((lane >> 4) << 3) + (lane & 7)) * STR2B + (((lane >> 3) & 1) << 4));
    uint32_t aWH = sb + G2_WH + boff;
    uint32_t aWL = sb + G2_WL + boff;

    const uint4* zh = (const uint4*)g_z_hi;
    const uint4* zl = (const uint4*)g_z_lo;

    for (int tile = blockIdx.x; tile < NT; tile += gridDim.x) {
        int row0 = tile << 7;
        int rv = min(128, N_NODES - row0);

        float acc[4][4][4];
        #pragma unroll
        for (int i = 0; i < 4; i++)
            #pragma unroll
            for (int j = 0; j < 4; j++)
                #pragma unroll
                for (int f = 0; f < 4; f++) acc[i][j][f] = 0.f;

        #pragma unroll 1
        for (int ch = 0; ch < 2; ch++) {
            __syncthreads();
            #pragma unroll 4
            for (int i = tid; i < 2048; i += 256) {
                int r = i >> 4, c = i & 15;
                uint4 vh = make_uint4(0, 0, 0, 0), vl = vh;
                if (r < rv) {
                    size_t si = (size_t)(row0 + r) * 32 + ch * 16 + c;
                    vh = zh[si]; vl = zl[si];
                }
                *(uint4*)(sm + G2_ZH + r * STR1B + c * 16) = vh;
                *(uint4*)(sm + G2_ZL + r * STR1B + c * 16) = vl;
            }
            __syncthreads();

            uint32_t chb = (uint32_t)ch * 256;  // 128 elems * 2B
            #pragma unroll 2
            for (int ks = 0; ks < 8; ks++) {
                uint32_t kb = ks << 5;
                uint32_t Ah[4][4], Alr[4][4], B[2][4];
                #pragma unroll
                for (int i = 0; i < 4; i++) {
                    LDSM_X4(Ah[i][0], Ah[i][1], Ah[i][2], Ah[i][3], aZH + i * (16 * STR1B) + kb);
                    LDSM_X4(Alr[i][0], Alr[i][1], Alr[i][2], Alr[i][3], aZL + i * (16 * STR1B) + kb);
                }
                #pragma unroll
                for (int j2 = 0; j2 < 2; j2++)
                    LDSM_X4(B[j2][0], B[j2][1], B[j2][2], B[j2][3],
                            aWH + j2 * (16 * STR2B) + chb + kb);
                #pragma unroll
                for (int i = 0; i < 4; i++)
                    #pragma unroll
                    for (int j = 0; j < 4; j++)
                        mma_bf16(acc[i][j][0], acc[i][j][1], acc[i][j][2], acc[i][j][3],
                                 Ah[i][0], Ah[i][1], Ah[i][2], Ah[i][3],
                                 B[j >> 1][(j & 1) * 2], B[j >> 1][(j & 1) * 2 + 1]);
                #pragma unroll
                for (int i = 0; i < 4; i++)
                    #pragma unroll
                    for (int j = 0; j < 4; j++)
                        mma_bf16(acc[i][j][0], acc[i][j][1], acc[i][j][2], acc[i][j][3],
                                 Alr[i][0], Alr[i][1], Alr[i][2], Alr[i][3],
                                 B[j >> 1][(j & 1) * 2], B[j >> 1][(j & 1) * 2 + 1]);
                #pragma unroll
                for (int j2 = 0; j2 < 2; j2++)
                    LDSM_X4(B[j2][0], B[j2][1], B[j2][2], B[j2][3],
                            aWL + j2 * (16 * STR2B) + chb + kb);
                #pragma unroll
                for (int i = 0; i < 4; i++)
                    #pragma unroll
                    for (int j = 0; j < 4; j++)
                        mma_bf16(acc[i][j][0], acc[i][j][1], acc[i][j][2], acc[i][j][3],
                                 Ah[i][0], Ah[i][1], Ah[i][2], Ah[i][3],
                                 B[j >> 1][(j & 1) * 2], B[j >> 1][(j & 1) * 2 + 1]);
            }
        }

        // epilogue: BN (+relu), fp32 store
        int q = lane & 3;
        #pragma unroll
        for (int i = 0; i < 4; i++) {
            #pragma unroll
            for (int hf = 0; hf < 2; hf++) {
                int r = row0 + m0 + i * 16 + (lane >> 2) + hf * 8;
                if (r < N_NODES) {
                    float* dst = out + (size_t)r * 128;
                    #pragma unroll
                    for (int j = 0; j < 4; j++) {
                        int c = n0 + j * 8 + 2 * q;
                        float z0 = fmaf(acc[i][j][hf * 2],     sAl[c],     sBe[c]);
                        float z1 = fmaf(acc[i][j][hf * 2 + 1], sAl[c + 1], sBe[c + 1]);
                        if (relu) { z0 = fmaxf(z0, 0.f); z1 = fmaxf(z1, 0.f); }
                        *(float2*)(dst + c) = make_float2(z0, z1);
                    }
                }
            }
        }
    }
}

// ---------------- launch ----------------------------------------------------------
extern "C" void kernel_launch(void* const* d_in, const int* in_sizes, int n_in,
                              void* d_out, int out_size) {
    const float* x     = (const float*)d_in[0];
    const int*   ei    = (const int*)d_in[1];
    const float* W1    = (const float*)d_in[2];
    const float* b1    = (const float*)d_in[3];
    const float* bn1_g = (const float*)d_in[4];
    const float* bn1_b = (const float*)d_in[5];
    const float* bn1_m = (const float*)d_in[6];
    const float* bn1_v = (const float*)d_in[7];
    const float* W2    = (const float*)d_in[8];
    const float* b2    = (const float*)d_in[9];
    const float* bno_g = (const float*)d_in[10];
    const float* bno_b = (const float*)d_in[11];
    const float* bno_m = (const float*)d_in[12];
    const float* bno_v = (const float*)d_in[13];
    float* out = (float*)d_out;

    cudaFuncSetAttribute(k_gemm1, cudaFuncAttributeMaxDynamicSharedMemorySize, SMEM1);
    cudaFuncSetAttribute(k_gemm2, cudaFuncAttributeMaxDynamicSharedMemorySize, SMEM2);

    const int* src = ei;
    const int* dst = ei + EDGES;

    k_wconv<<<(2 * LAYERS * 32768 + 255) / 256, 256>>>(W1, W2);
    k_zero<<<(N_NODES + 255) / 256, 256>>>();
    k_hist<<<(EDGES + 255) / 256, 256>>>(dst);
    k_scan<<<1, 1024>>>();
    k_fill<<<(EDGES + 255) / 256, 256>>>(src, dst);

    const float* h = x;
    for (int l = 0; l < LAYERS; l++) {
        k_aggregate<<<(N_NODES * 32 + 255) / 256, 256>>>(h);
        k_gemm1<<<GRID_G, 256, SMEM1>>>(l, b1 + (size_t)l * 256,
                bn1_g + (size_t)l * 256, bn1_b + (size_t)l * 256,
                bn1_m + (size_t)l * 256, bn1_v + (size_t)l * 256);
        k_gemm2<<<GRID_G, 256, SMEM2>>>(l, b2 + (size_t)l * 128,
                bno_g + (size_t)l * 128, bno_b + (size_t)l * 128,
                bno_m + (size_t)l * 128, bno_v + (size_t)l * 128,
                out, (l != LAYERS - 1) ? 1 : 0);
        h = out;
    }
}

// round 4
// speedup vs baseline: 1.4962x; 1.0301x over previous
#include <cuda_runtime.h>
#include <cuda_bf16.h>
#include <cstdint>

#define N_NODES 100000
#define EDGES   640000
#define LAYERS  5
#define BN_EPS  1e-5f
#define NT      782          // ceil(100000/128)
#define GRID_G  148
#define NSCAN   98           // ceil(100000/1024)

// ---------------- static scratch ------------------------------------------------
__device__ __nv_bfloat16 g_a_hi[(size_t)N_NODES * 128];
__device__ __nv_bfloat16 g_a_lo[(size_t)N_NODES * 128];
__device__ __nv_bfloat16 g_z_hi[(size_t)N_NODES * 256];
__device__ __nv_bfloat16 g_z_lo[(size_t)N_NODES * 256];
__device__ __nv_bfloat16 g_w1t[LAYERS * 2 * 32768];   // Wt1: [l][term][n=256][k=128]
__device__ __nv_bfloat16 g_w2t[LAYERS * 2 * 32768];   // Wt2: [l][term][n=128][k=256]
__device__ int g_rowptr[N_NODES + 1];
__device__ int g_cnt[N_NODES];
__device__ int g_cursor[N_NODES];
__device__ int g_srcs[EDGES];
__device__ int g_part[NSCAN];
__device__ int g_parts[NSCAN];

// ---------------- helpers -------------------------------------------------------
__device__ __forceinline__ uint32_t smem_u32(const void* p) {
    uint32_t a;
    asm("{ .reg .u64 t; cvta.to.shared.u64 t, %1; cvt.u32.u64 %0, t; }" : "=r"(a) : "l"(p));
    return a;
}
__device__ __forceinline__ uint32_t pack_bf(__nv_bfloat16 a, __nv_bfloat16 b) {
    return ((uint32_t)__bfloat16_as_ushort(b) << 16) | (uint32_t)__bfloat16_as_ushort(a);
}
__device__ __forceinline__ void split_bf(float x, __nv_bfloat16& h, __nv_bfloat16& l) {
    h = __float2bfloat16(x);
    l = __float2bfloat16(x - __bfloat162float(h));
}

#define LDSM_X4(r0, r1, r2, r3, addr) \
    asm volatile("ldmatrix.sync.aligned.m8n8.x4.shared.b16 {%0,%1,%2,%3}, [%4];" \
        : "=r"(r0), "=r"(r1), "=r"(r2), "=r"(r3) : "r"(addr))

__device__ __forceinline__ void mma_bf16(float& c0, float& c1, float& c2, float& c3,
        uint32_t a0, uint32_t a1, uint32_t a2, uint32_t a3, uint32_t b0, uint32_t b1) {
    asm volatile("mma.sync.aligned.m16n8k16.row.col.f32.bf16.bf16.f32 "
        "{%0,%1,%2,%3}, {%4,%5,%6,%7}, {%8,%9}, {%0,%1,%2,%3};"
        : "+f"(c0), "+f"(c1), "+f"(c2), "+f"(c3)
        : "r"(a0), "r"(a1), "r"(a2), "r"(a3), "r"(b0), "r"(b1));
}

__device__ __forceinline__ void cp16(uint32_t dst, const void* src, uint32_t srcsz) {
    asm volatile("cp.async.ca.shared.global [%0], [%1], 16, %2;"
                 :: "r"(dst), "l"(src), "r"(srcsz) : "memory");
}
#define CP_COMMIT() asm volatile("cp.async.commit_group;" ::: "memory")
__device__ __forceinline__ void cp_wait_dyn(int n) {
    switch (n) {
        case 0: asm volatile("cp.async.wait_group 0;" ::: "memory"); break;
        case 2: asm volatile("cp.async.wait_group 2;" ::: "memory"); break;
        case 4: asm volatile("cp.async.wait_group 4;" ::: "memory"); break;
        case 6: asm volatile("cp.async.wait_group 6;" ::: "memory"); break;
        default: asm volatile("cp.async.wait_group 0;" ::: "memory"); break;
    }
}

// ---------------- CSR build ------------------------------------------------------
__global__ void k_zero() {
    int i = blockIdx.x * blockDim.x + threadIdx.x;
    if (i < N_NODES) { g_cnt[i] = 0; g_cursor[i] = 0; }
}
__global__ void k_hist(const int* __restrict__ dst) {
    int e = blockIdx.x * blockDim.x + threadIdx.x;
    if (e < EDGES) atomicAdd(&g_cnt[dst[e]], 1);
}
// block-level inclusive scan of g_cnt -> g_rowptr[i+1] (local), block sums -> g_part
__global__ void k_scan_a() {
    __shared__ int s[1024];
    int t = threadIdx.x, b = blockIdx.x;
    int i = b * 1024 + t;
    int v = (i < N_NODES) ? g_cnt[i] : 0;
    s[t] = v;
    __syncthreads();
    #pragma unroll
    for (int off = 1; off < 1024; off <<= 1) {
        int u = (t >= off) ? s[t - off] : 0;
        __syncthreads();
        s[t] += u;
        __syncthreads();
    }
    if (i < N_NODES) g_rowptr[i + 1] = s[t];
    if (t == 1023) g_part[b] = s[t];
}
__global__ void k_scan_b() {
    if (threadIdx.x == 0) {
        int acc = 0;
        for (int b = 0; b < NSCAN; b++) { g_parts[b] = acc; acc += g_part[b]; }
    }
}
__global__ void k_scan_c() {
    int t = threadIdx.x, b = blockIdx.x;
    int i = b * 1024 + t;
    if (i < N_NODES) g_rowptr[i + 1] += g_parts[b];
    if (i == 0) g_rowptr[0] = 0;
}
__global__ void k_fill(const int* __restrict__ src, const int* __restrict__ dst) {
    int e = blockIdx.x * blockDim.x + threadIdx.x;
    if (e < EDGES) {
        int d = dst[e];
        int p = g_rowptr[d] + atomicAdd(&g_cursor[d], 1);
        g_srcs[p] = src[e];
    }
}

// ---------------- W -> split-bf16 transposed images ------------------------------
__global__ void k_wconv(const float* __restrict__ W1, const float* __restrict__ W2) {
    int i = blockIdx.x * blockDim.x + threadIdx.x;
    const int TOT = LAYERS * 32768;
    if (i < TOT) {
        int l = i >> 15, r = i & 32767;
        int k = r >> 8, n = r & 255;           // W1[l][k][n]
        __nv_bfloat16 hi, lo;
        split_bf(W1[i], hi, lo);
        g_w1t[(size_t)l * 65536 + n * 128 + k] = hi;
        g_w1t[(size_t)l * 65536 + 32768 + n * 128 + k] = lo;
    } else if (i < 2 * TOT) {
        int j = i - TOT;
        int l = j >> 15, r = j & 32767;
        int k = r >> 7, n = r & 127;           // W2[l][k][n]
        __nv_bfloat16 hi, lo;
        split_bf(W2[j], hi, lo);
        g_w2t[(size_t)l * 65536 + n * 256 + k] = hi;
        g_w2t[(size_t)l * 65536 + 32768 + n * 256 + k] = lo;
    }
}

// ---------------- aggregation: agg = h_i + sum h_j -> split bf16 -----------------
__global__ void k_aggregate(const float* __restrict__ h) {
    int gw = (blockIdx.x * blockDim.x + threadIdx.x) >> 5;
    int lane = threadIdx.x & 31;
    if (gw >= N_NODES) return;
    const float4* hv = (const float4*)h;
    float4 acc = __ldg(&hv[(size_t)gw * 32 + lane]);
    int e0 = g_rowptr[gw], e1 = g_rowptr[gw + 1];
    for (int e = e0; e < e1; e++) {
        int j = g_srcs[e];
        float4 v = __ldg(&hv[(size_t)j * 32 + lane]);
        acc.x += v.x; acc.y += v.y; acc.z += v.z; acc.w += v.w;
    }
    __nv_bfloat16 h0, h1, h2, h3, l0, l1, l2, l3;
    split_bf(acc.x, h0, l0); split_bf(acc.y, h1, l1);
    split_bf(acc.z, h2, l2); split_bf(acc.w, h3, l3);
    uint2 ph, pl;
    ph.x = pack_bf(h0, h1); ph.y = pack_bf(h2, h3);
    pl.x = pack_bf(l0, l1); pl.y = pack_bf(l2, l3);
    ((uint2*)g_a_hi)[(size_t)gw * 32 + lane] = ph;
    ((uint2*)g_a_lo)[(size_t)gw * 32 + lane] = pl;
}

// ---------------- SMEM layouts ----------------------------------------------------
#define STR1B    272
#define G1_WH    0
#define G1_WL    69632
#define G1_AH    139264
#define G1_AL    174080
#define G1_ALPHA 208896
#define G1_BETA  209920
#define SMEM1    210944
#define STR2B    528
#define G2_WH    0
#define G2_WL    67584
#define G2_ZH    135168
#define G2_ZL    169984
#define G2_ALPHA 204800
#define G2_BETA  205312
#define SMEM2    205824

// ---- cp.async slice issuers (8 groups of k16 slices; 2 x 16B per thread/slice) --
// GEMM1 A: global row = 256 bytes (128 bf16)
__device__ __forceinline__ void g1_issue(uint32_t sb, int tid, int row0) {
    int r = tid >> 1, c = tid & 1;
    int gr = row0 + r;
    uint32_t p = (gr < N_NODES) ? 16u : 0u;
    const char* gh = (const char*)g_a_hi + (size_t)gr * 256 + c * 16;
    const char* gl = (const char*)g_a_lo + (size_t)gr * 256 + c * 16;
    uint32_t dh = sb + G1_AH + r * STR1B + c * 16;
    uint32_t dl = sb + G1_AL + r * STR1B + c * 16;
    #pragma unroll
    for (int s = 0; s < 8; s++) {
        cp16(dh + s * 32, gh + s * 32, p);
        cp16(dl + s * 32, gl + s * 32, p);
        CP_COMMIT();
    }
}
// GEMM2 Z chunk: global row = 512 bytes (256 bf16), chunk ch in {0,1}
__device__ __forceinline__ void g2_issue(uint32_t sb, int tid, int row0, int ch) {
    int r = tid >> 1, c = tid & 1;
    int gr = row0 + r;
    uint32_t p = (gr < N_NODES) ? 16u : 0u;
    const char* gh = (const char*)g_z_hi + (size_t)gr * 512 + ch * 256 + c * 16;
    const char* gl = (const char*)g_z_lo + (size_t)gr * 512 + ch * 256 + c * 16;
    uint32_t dh = sb + G2_ZH + r * STR1B + c * 16;
    uint32_t dl = sb + G2_ZL + r * STR1B + c * 16;
    #pragma unroll
    for (int s = 0; s < 8; s++) {
        cp16(dh + s * 32, gh + s * 32, p);
        cp16(dl + s * 32, gl + s * 32, p);
        CP_COMMIT();
    }
}

// ---------------- GEMM1: z = relu(BN1(agg @ W1 + b1)),  [N,128]x[128,256] --------
__global__ void __launch_bounds__(256, 1) k_gemm1(
    int layer, const float* __restrict__ bias,
    const float* __restrict__ bn_g, const float* __restrict__ bn_b,
    const float* __restrict__ bn_m, const float* __restrict__ bn_v)
{
    extern __shared__ char sm[];
    uint32_t sb = smem_u32(sm);
    int tid = threadIdx.x, lane = tid & 31, wid = tid >> 5;

    // prefetch first A tile while loading W
    g1_issue(sb, tid, blockIdx.x << 7);

    {
        const uint4* s = (const uint4*)(g_w1t + (size_t)layer * 65536);
        #pragma unroll 4
        for (int i = tid; i < 4096; i += 256) {
            int r = i >> 4, c = i & 15;
            *(uint4*)(sm + G1_WH + r * STR1B + c * 16) = s[i];
            *(uint4*)(sm + G1_WL + r * STR1B + c * 16) = s[i + 4096];
        }
    }
    float* sAl = (float*)(sm + G1_ALPHA);
    float* sBe = (float*)(sm + G1_BETA);
    if (tid < 256) {
        int c = tid;
        float s = bn_g[c] * rsqrtf(bn_v[c] + BN_EPS);
        sAl[c] = s;
        sBe[c] = (bias[c] - bn_m[c]) * s + bn_b[c];
    }
    __syncthreads();

    int m0 = (wid >> 2) * 64, n0 = (wid & 3) * 64;
    uint32_t aoff = (uint32_t)((m0 + (lane & 15)) * STR1B + ((lane >> 4) << 4));
    uint32_t aAH = sb + G1_AH + aoff;
    uint32_t aAL = sb + G1_AL + aoff;
    uint32_t boff = (uint32_t)((n0 + ((lane >> 4) << 3) + (lane & 7)) * STR1B + (((lane >> 3) & 1) << 4));
    uint32_t aWH = sb + G1_WH + boff;
    uint32_t aWL = sb + G1_WL + boff;

    for (int tile = blockIdx.x; tile < NT; tile += gridDim.x) {
        int row0 = tile << 7;

        float acc[4][8][4];
        #pragma unroll
        for (int i = 0; i < 4; i++)
            #pragma unroll
            for (int j = 0; j < 8; j++)
                #pragma unroll
                for (int f = 0; f < 4; f++) acc[i][j][f] = 0.f;

        #pragma unroll
        for (int kp = 0; kp < 4; kp++) {
            cp_wait_dyn(6 - 2 * kp);
            __syncthreads();
            #pragma unroll
            for (int kq = 0; kq < 2; kq++) {
                int ks = kp * 2 + kq;
                uint32_t kb = ks << 5;
                uint32_t Ah[4][4], Alr[4][4], B[4][4];
                #pragma unroll
                for (int i = 0; i < 4; i++) {
                    LDSM_X4(Ah[i][0], Ah[i][1], Ah[i][2], Ah[i][3], aAH + i * (16 * STR1B) + kb);
                    LDSM_X4(Alr[i][0], Alr[i][1], Alr[i][2], Alr[i][3], aAL + i * (16 * STR1B) + kb);
                }
                #pragma unroll
                for (int j2 = 0; j2 < 4; j2++)
                    LDSM_X4(B[j2][0], B[j2][1], B[j2][2], B[j2][3], aWH + j2 * (16 * STR1B) + kb);
                #pragma unroll
                for (int i = 0; i < 4; i++)
                    #pragma unroll
                    for (int j = 0; j < 8; j++)
                        mma_bf16(acc[i][j][0], acc[i][j][1], acc[i][j][2], acc[i][j][3],
                                 Ah[i][0], Ah[i][1], Ah[i][2], Ah[i][3],
                                 B[j >> 1][(j & 1) * 2], B[j >> 1][(j & 1) * 2 + 1]);
                #pragma unroll
                for (int i = 0; i < 4; i++)
                    #pragma unroll
                    for (int j = 0; j < 8; j++)
                        mma_bf16(acc[i][j][0], acc[i][j][1], acc[i][j][2], acc[i][j][3],
                                 Alr[i][0], Alr[i][1], Alr[i][2], Alr[i][3],
                                 B[j >> 1][(j & 1) * 2], B[j >> 1][(j & 1) * 2 + 1]);
                #pragma unroll
                for (int j2 = 0; j2 < 4; j2++)
                    LDSM_X4(B[j2][0], B[j2][1], B[j2][2], B[j2][3], aWL + j2 * (16 * STR1B) + kb);
                #pragma unroll
                for (int i = 0; i < 4; i++)
                    #pragma unroll
                    for (int j = 0; j < 8; j++)
                        mma_bf16(acc[i][j][0], acc[i][j][1], acc[i][j][2], acc[i][j][3],
                                 Ah[i][0], Ah[i][1], Ah[i][2], Ah[i][3],
                                 B[j >> 1][(j & 1) * 2], B[j >> 1][(j & 1) * 2 + 1]);
            }
        }
        __syncthreads();                    // all warps done reading A smem
        g1_issue(sb, tid, (tile + gridDim.x) << 7);   // prefetch next tile

        // epilogue: BN + relu + split-bf16 store (overlaps with prefetch)
        int q = lane & 3;
        uint32_t* zh = (uint32_t*)g_z_hi;
        uint32_t* zl = (uint32_t*)g_z_lo;
        #pragma unroll
        for (int i = 0; i < 4; i++) {
            #pragma unroll
            for (int hf = 0; hf < 2; hf++) {
                int r = row0 + m0 + i * 16 + (lane >> 2) + hf * 8;
                if (r < N_NODES) {
                    size_t rb = (size_t)r * 128 + (n0 >> 1) + q;
                    #pragma unroll
                    for (int j = 0; j < 8; j++) {
                        int c = n0 + j * 8 + 2 * q;
                        float z0 = fmaxf(fmaf(acc[i][j][hf * 2],     sAl[c],     sBe[c]),     0.f);
                        float z1 = fmaxf(fmaf(acc[i][j][hf * 2 + 1], sAl[c + 1], sBe[c + 1]), 0.f);
                        __nv_bfloat16 h0, h1, l0, l1;
                        split_bf(z0, h0, l0); split_bf(z1, h1, l1);
                        zh[rb + j * 4] = pack_bf(h0, h1);
                        zl[rb + j * 4] = pack_bf(l0, l1);
                    }
                }
            }
        }
    }
}

// ---------------- GEMM2: h = BN_o(z @ W2 + b2)(+relu),  [N,256]x[256,128] --------
__global__ void __launch_bounds__(256, 1) k_gemm2(
    int layer, const float* __restrict__ bias,
    const float* __restrict__ bn_g, const float* __restrict__ bn_b,
    const float* __restrict__ bn_m, const float* __restrict__ bn_v,
    float* __restrict__ out, int relu)
{
    extern __shared__ char sm[];
    uint32_t sb = smem_u32(sm);
    int tid = threadIdx.x, lane = tid & 31, wid = tid >> 5;

    g2_issue(sb, tid, blockIdx.x << 7, 0);

    {
        const uint4* s = (const uint4*)(g_w2t + (size_t)layer * 65536);
        #pragma unroll 4
        for (int i = tid; i < 4096; i += 256) {
            int r = i >> 5, c = i & 31;
            *(uint4*)(sm + G2_WH + r * STR2B + c * 16) = s[i];
            *(uint4*)(sm + G2_WL + r * STR2B + c * 16) = s[i + 4096];
        }
    }
    float* sAl = (float*)(sm + G2_ALPHA);
    float* sBe = (float*)(sm + G2_BETA);
    if (tid < 128) {
        int c = tid;
        float s = bn_g[c] * rsqrtf(bn_v[c] + BN_EPS);
        sAl[c] = s;
        sBe[c] = (bias[c] - bn_m[c]) * s + bn_b[c];
    }
    __syncthreads();

    int m0 = (wid >> 2) * 64, n0 = (wid & 3) * 32;
    uint32_t aoff = (uint32_t)((m0 + (lane & 15)) * STR1B + ((lane >> 4) << 4));
    uint32_t aZH = sb + G2_ZH + aoff;
    uint32_t aZL = sb + G2_ZL + aoff;
    uint32_t boff = (uint32_t)((n0 + ((lane >> 4) << 3) + (lane & 7)) * STR2B + (((lane >> 3) & 1) << 4));
    uint32_t aWH = sb + G2_WH + boff;
    uint32_t aWL = sb + G2_WL + boff;

    for (int tile = blockIdx.x; tile < NT; tile += gridDim.x) {
        int row0 = tile << 7;

        float acc[4][4][4];
        #pragma unroll
        for (int i = 0; i < 4; i++)
            #pragma unroll
            for (int j = 0; j < 4; j++)
                #pragma unroll
                for (int f = 0; f < 4; f++) acc[i][j][f] = 0.f;

        #pragma unroll 1
        for (int ch = 0; ch < 2; ch++) {
            uint32_t chb = (uint32_t)ch * 256;
            #pragma unroll
            for (int kp = 0; kp < 4; kp++) {
                cp_wait_dyn(6 - 2 * kp);
                __syncthreads();
                #pragma unroll
                for (int kq = 0; kq < 2; kq++) {
                    int ks = kp * 2 + kq;
                    uint32_t kb = ks << 5;
                    uint32_t Ah[4][4], Alr[4][4], B[2][4];
                    #pragma unroll
                    for (int i = 0; i < 4; i++) {
                        LDSM_X4(Ah[i][0], Ah[i][1], Ah[i][2], Ah[i][3], aZH + i * (16 * STR1B) + kb);
                        LDSM_X4(Alr[i][0], Alr[i][1], Alr[i][2], Alr[i][3], aZL + i * (16 * STR1B) + kb);
                    }
                    #pragma unroll
                    for (int j2 = 0; j2 < 2; j2++)
                        LDSM_X4(B[j2][0], B[j2][1], B[j2][2], B[j2][3],
                                aWH + j2 * (16 * STR2B) + chb + kb);
                    #pragma unroll
                    for (int i = 0; i < 4; i++)
                        #pragma unroll
                        for (int j = 0; j < 4; j++)
                            mma_bf16(acc[i][j][0], acc[i][j][1], acc[i][j][2], acc[i][j][3],
                                     Ah[i][0], Ah[i][1], Ah[i][2], Ah[i][3],
                                     B[j >> 1][(j & 1) * 2], B[j >> 1][(j & 1) * 2 + 1]);
                    #pragma unroll
                    for (int i = 0; i < 4; i++)
                        #pragma unroll
                        for (int j = 0; j < 4; j++)
                            mma_bf16(acc[i][j][0], acc[i][j][1], acc[i][j][2], acc[i][j][3],
                                     Alr[i][0], Alr[i][1], Alr[i][2], Alr[i][3],
                                     B[j >> 1][(j & 1) * 2], B[j >> 1][(j & 1) * 2 + 1]);
                    #pragma unroll
                    for (int j2 = 0; j2 < 2; j2++)
                        LDSM_X4(B[j2][0], B[j2][1], B[j2][2], B[j2][3],
                                aWL + j2 * (16 * STR2B) + chb + kb);
                    #pragma unroll
                    for (int i = 0; i < 4; i++)
                        #pragma unroll
                        for (int j = 0; j < 4; j++)
                            mma_bf16(acc[i][j][0], acc[i][j][1], acc[i][j][2], acc[i][j][3],
                                     Ah[i][0], Ah[i][1], Ah[i][2], Ah[i][3],
                                     B[j >> 1][(j & 1) * 2], B[j >> 1][(j & 1) * 2 + 1]);
                }
            }
            __syncthreads();                 // chunk consumed
            if (ch == 0)
                g2_issue(sb, tid, row0, 1);                       // chunk1 of this tile
            else
                g2_issue(sb, tid, (tile + gridDim.x) << 7, 0);    // chunk0 of next tile
        }

        // epilogue: BN (+relu), fp32 store (overlaps with next-tile prefetch)
        int q = lane & 3;
        #pragma unroll
        for (int i = 0; i < 4; i++) {
            #pragma unroll
            for (int hf = 0; hf < 2; hf++) {
                int r = row0 + m0 + i * 16 + (lane >> 2) + hf * 8;
                if (r < N_NODES) {
                    float* dst = out + (size_t)r * 128;
                    #pragma unroll
                    for (int j = 0; j < 4; j++) {
                        int c = n0 + j * 8 + 2 * q;
                        float z0 = fmaf(acc[i][j][hf * 2],     sAl[c],     sBe[c]);
                        float z1 = fmaf(acc[i][j][hf * 2 + 1], sAl[c + 1], sBe[c + 1]);
                        if (relu) { z0 = fmaxf(z0, 0.f); z1 = fmaxf(z1, 0.f); }
                        *(float2*)(dst + c) = make_float2(z0, z1);
                    }
                }
            }
        }
    }
}

// ---------------- launch ----------------------------------------------------------
extern "C" void kernel_launch(void* const* d_in, const int* in_sizes, int n_in,
                              void* d_out, int out_size) {
    const float* x     = (const float*)d_in[0];
    const int*   ei    = (const int*)d_in[1];
    const float* W1    = (const float*)d_in[2];
    const float* b1    = (const float*)d_in[3];
    const float* bn1_g = (const float*)d_in[4];
    const float* bn1_b = (const float*)d_in[5];
    const float* bn1_m = (const float*)d_in[6];
    const float* bn1_v = (const float*)d_in[7];
    const float* W2    = (const float*)d_in[8];
    const float* b2    = (const float*)d_in[9];
    const float* bno_g = (const float*)d_in[10];
    const float* bno_b = (const float*)d_in[11];
    const float* bno_m = (const float*)d_in[12];
    const float* bno_v = (const float*)d_in[13];
    float* out = (float*)d_out;

    cudaFuncSetAttribute(k_gemm1, cudaFuncAttributeMaxDynamicSharedMemorySize, SMEM1);
    cudaFuncSetAttribute(k_gemm2, cudaFuncAttributeMaxDynamicSharedMemorySize, SMEM2);

    const int* src = ei;
    const int* dst = ei + EDGES;

    k_wconv<<<(2 * LAYERS * 32768 + 255) / 256, 256>>>(W1, W2);
    k_zero<<<(N_NODES + 255) / 256, 256>>>();
    k_hist<<<(EDGES + 255) / 256, 256>>>(dst);
    k_scan_a<<<NSCAN, 1024>>>();
    k_scan_b<<<1, 32>>>();
    k_scan_c<<<NSCAN, 1024>>>();
    k_fill<<<(EDGES + 255) / 256, 256>>>(src, dst);

    const float* h = x;
    for (int l = 0; l < LAYERS; l++) {
        k_aggregate<<<(N_NODES * 32 + 255) / 256, 256>>>(h);
        k_gemm1<<<GRID_G, 256, SMEM1>>>(l, b1 + (size_t)l * 256,
                bn1_g + (size_t)l * 256, bn1_b + (size_t)l * 256,
                bn1_m + (size_t)l * 256, bn1_v + (size_t)l * 256);
        k_gemm2<<<GRID_G, 256, SMEM2>>>(l, b2 + (size_t)l * 128,
                bno_g + (size_t)l * 128, bno_b + (size_t)l * 128,
                bno_m + (size_t)l * 128, bno_v + (size_t)l * 128,
                out, (l != LAYERS - 1) ? 1 : 0);
        h = out;
    }
}

// round 5
// speedup vs baseline: 1.5339x; 1.0252x over previous
#include <cuda_runtime.h>
#include <cuda_bf16.h>
#include <cstdint>

#define N_NODES 100000
#define EDGES   640000
#define LAYERS  5
#define BN_EPS  1e-5f
#define NT      782          // ceil(100000/128)
#define GRID_G  148
#define NSCAN   98           // ceil(100000/1024)

// ---------------- static scratch ------------------------------------------------
__device__ __nv_bfloat16 g_a_hi[(size_t)N_NODES * 128];
__device__ __nv_bfloat16 g_a_lo[(size_t)N_NODES * 128];
__device__ __nv_bfloat16 g_z_hi[(size_t)N_NODES * 256];
__device__ __nv_bfloat16 g_z_lo[(size_t)N_NODES * 256];
__device__ __nv_bfloat16 g_w1t[LAYERS * 2 * 32768];   // Wt1: [l][term][n=256][k=128]
__device__ __nv_bfloat16 g_w2t[LAYERS * 2 * 32768];   // Wt2: [l][term][n=128][k=256]
__device__ int g_rowptr[N_NODES + 1];
__device__ int g_cnt[N_NODES];
__device__ int g_cursor[N_NODES];
__device__ int g_srcs[EDGES];
__device__ int g_part[NSCAN];
__device__ int g_parts[NSCAN];

// ---------------- helpers -------------------------------------------------------
__device__ __forceinline__ uint32_t smem_u32(const void* p) {
    uint32_t a;
    asm("{ .reg .u64 t; cvta.to.shared.u64 t, %1; cvt.u32.u64 %0, t; }" : "=r"(a) : "l"(p));
    return a;
}
__device__ __forceinline__ uint32_t pack_bf(__nv_bfloat16 a, __nv_bfloat16 b) {
    return ((uint32_t)__bfloat16_as_ushort(b) << 16) | (uint32_t)__bfloat16_as_ushort(a);
}
__device__ __forceinline__ void split_bf(float x, __nv_bfloat16& h, __nv_bfloat16& l) {
    h = __float2bfloat16(x);
    l = __float2bfloat16(x - __bfloat162float(h));
}

#define LDSM_X4(r0, r1, r2, r3, addr) \
    asm volatile("ldmatrix.sync.aligned.m8n8.x4.shared.b16 {%0,%1,%2,%3}, [%4];" \
        : "=r"(r0), "=r"(r1), "=r"(r2), "=r"(r3) : "r"(addr))

__device__ __forceinline__ void mma_bf16(float& c0, float& c1, float& c2, float& c3,
        uint32_t a0, uint32_t a1, uint32_t a2, uint32_t a3, uint32_t b0, uint32_t b1) {
    asm volatile("mma.sync.aligned.m16n8k16.row.col.f32.bf16.bf16.f32 "
        "{%0,%1,%2,%3}, {%4,%5,%6,%7}, {%8,%9}, {%0,%1,%2,%3};"
        : "+f"(c0), "+f"(c1), "+f"(c2), "+f"(c3)
        : "r"(a0), "r"(a1), "r"(a2), "r"(a3), "r"(b0), "r"(b1));
}

__device__ __forceinline__ void cp16(uint32_t dst, const void* src, uint32_t srcsz) {
    asm volatile("cp.async.ca.shared.global [%0], [%1], 16, %2;"
                 :: "r"(dst), "l"(src), "r"(srcsz) : "memory");
}
#define CP_COMMIT() asm volatile("cp.async.commit_group;" ::: "memory")
__device__ __forceinline__ void cp_wait_dyn(int n) {
    switch (n) {
        case 0: asm volatile("cp.async.wait_group 0;" ::: "memory"); break;
        case 2: asm volatile("cp.async.wait_group 2;" ::: "memory"); break;
        case 4: asm volatile("cp.async.wait_group 4;" ::: "memory"); break;
        case 6: asm volatile("cp.async.wait_group 6;" ::: "memory"); break;
        default: asm volatile("cp.async.wait_group 0;" ::: "memory"); break;
    }
}

// ---------------- CSR build ------------------------------------------------------
__global__ void k_zero() {
    int i = blockIdx.x * blockDim.x + threadIdx.x;
    if (i < N_NODES) { g_cnt[i] = 0; g_cursor[i] = 0; }
}
__global__ void k_hist(const int* __restrict__ dst) {
    int e = blockIdx.x * blockDim.x + threadIdx.x;
    if (e < EDGES) atomicAdd(&g_cnt[dst[e]], 1);
}
__global__ void k_scan_a() {
    __shared__ int s[1024];
    int t = threadIdx.x, b = blockIdx.x;
    int i = b * 1024 + t;
    int v = (i < N_NODES) ? g_cnt[i] : 0;
    s[t] = v;
    __syncthreads();
    #pragma unroll
    for (int off = 1; off < 1024; off <<= 1) {
        int u = (t >= off) ? s[t - off] : 0;
        __syncthreads();
        s[t] += u;
        __syncthreads();
    }
    if (i < N_NODES) g_rowptr[i + 1] = s[t];
    if (t == 1023) g_part[b] = s[t];
}
__global__ void k_scan_b() {
    if (threadIdx.x == 0) {
        int acc = 0;
        for (int b = 0; b < NSCAN; b++) { g_parts[b] = acc; acc += g_part[b]; }
    }
}
__global__ void k_scan_c() {
    int t = threadIdx.x, b = blockIdx.x;
    int i = b * 1024 + t;
    if (i < N_NODES) g_rowptr[i + 1] += g_parts[b];
    if (i == 0) g_rowptr[0] = 0;
}
__global__ void k_fill(const int* __restrict__ src, const int* __restrict__ dst) {
    int e = blockIdx.x * blockDim.x + threadIdx.x;
    if (e < EDGES) {
        int d = dst[e];
        int p = g_rowptr[d] + atomicAdd(&g_cursor[d], 1);
        g_srcs[p] = src[e];
    }
}

// ---------------- W -> split-bf16 transposed images ------------------------------
__global__ void k_wconv(const float* __restrict__ W1, const float* __restrict__ W2) {
    int i = blockIdx.x * blockDim.x + threadIdx.x;
    const int TOT = LAYERS * 32768;
    if (i < TOT) {
        int l = i >> 15, r = i & 32767;
        int k = r >> 8, n = r & 255;           // W1[l][k][n]
        __nv_bfloat16 hi, lo;
        split_bf(W1[i], hi, lo);
        g_w1t[(size_t)l * 65536 + n * 128 + k] = hi;
        g_w1t[(size_t)l * 65536 + 32768 + n * 128 + k] = lo;
    } else if (i < 2 * TOT) {
        int j = i - TOT;
        int l = j >> 15, r = j & 32767;
        int k = r >> 7, n = r & 127;           // W2[l][k][n]
        __nv_bfloat16 hi, lo;
        split_bf(W2[j], hi, lo);
        g_w2t[(size_t)l * 65536 + n * 256 + k] = hi;
        g_w2t[(size_t)l * 65536 + 32768 + n * 256 + k] = lo;
    }
}

// ---------------- aggregation: agg = h_i + sum h_j -> split bf16 -----------------
__global__ void k_aggregate(const float* __restrict__ h) {
    int gw = (blockIdx.x * blockDim.x + threadIdx.x) >> 5;
    int lane = threadIdx.x & 31;
    if (gw >= N_NODES) return;
    const float4* hv = (const float4*)h;
    float4 acc = __ldg(&hv[(size_t)gw * 32 + lane]);
    int e0 = g_rowptr[gw], e1 = g_rowptr[gw + 1];
    for (int e = e0; e < e1; e++) {
        int j = g_srcs[e];
        float4 v = __ldg(&hv[(size_t)j * 32 + lane]);
        acc.x += v.x; acc.y += v.y; acc.z += v.z; acc.w += v.w;
    }
    __nv_bfloat16 h0, h1, h2, h3, l0, l1, l2, l3;
    split_bf(acc.x, h0, l0); split_bf(acc.y, h1, l1);
    split_bf(acc.z, h2, l2); split_bf(acc.w, h3, l3);
    uint2 ph, pl;
    ph.x = pack_bf(h0, h1); ph.y = pack_bf(h2, h3);
    pl.x = pack_bf(l0, l1); pl.y = pack_bf(l2, l3);
    ((uint2*)g_a_hi)[(size_t)gw * 32 + lane] = ph;
    ((uint2*)g_a_lo)[(size_t)gw * 32 + lane] = pl;
}

// ---------------- SMEM layouts ----------------------------------------------------
#define STR1B    272
#define G1_WH    0
#define G1_WL    69632
#define G1_AH    139264
#define G1_AL    174080
#define G1_ALPHA 208896
#define G1_BETA  209920
#define SMEM1    210944
#define STR2B    528
#define G2_WH    0
#define G2_WL    67584
#define G2_ZH    135168
#define G2_ZL    169984
#define G2_ALPHA 204800
#define G2_BETA  205312
#define SMEM2    205824

// ---- cp.async slice issuers: 8 groups (one per k16 slice); 1 cp16/thread/slice --
// tid<256 -> hi term, tid>=256 -> lo term; r = (tid&255)>>1, c = tid&1
__device__ __forceinline__ void g1_issue(uint32_t sb, int tid, int row0) {
    int hl = tid >> 8;
    int t = tid & 255;
    int r = t >> 1, c = t & 1;
    int gr = row0 + r;
    uint32_t p = (gr < N_NODES) ? 16u : 0u;
    const char* gsrc = (const char*)(hl ? g_a_lo : g_a_hi) + (size_t)gr * 256 + c * 16;
    uint32_t dsm = sb + (hl ? G1_AL : G1_AH) + r * STR1B + c * 16;
    #pragma unroll
    for (int s = 0; s < 8; s++) {
        cp16(dsm + s * 32, gsrc + s * 32, p);
        CP_COMMIT();
    }
}
__device__ __forceinline__ void g2_issue(uint32_t sb, int tid, int row0, int ch) {
    int hl = tid >> 8;
    int t = tid & 255;
    int r = t >> 1, c = t & 1;
    int gr = row0 + r;
    uint32_t p = (gr < N_NODES) ? 16u : 0u;
    const char* gsrc = (const char*)(hl ? g_z_lo : g_z_hi) + (size_t)gr * 512 + ch * 256 + c * 16;
    uint32_t dsm = sb + (hl ? G2_ZL : G2_ZH) + r * STR1B + c * 16;
    #pragma unroll
    for (int s = 0; s < 8; s++) {
        cp16(dsm + s * 32, gsrc + s * 32, p);
        CP_COMMIT();
    }
}

// ---------------- GEMM1: z = relu(BN1(agg @ W1 + b1)),  [N,128]x[128,256] --------
// 512 threads, 16 warps in 4x4 grid; warp tile 32(m) x 64(n)
__global__ void __launch_bounds__(512, 1) k_gemm1(
    int layer, const float* __restrict__ bias,
    const float* __restrict__ bn_g, const float* __restrict__ bn_b,
    const float* __restrict__ bn_m, const float* __restrict__ bn_v)
{
    extern __shared__ char sm[];
    uint32_t sb = smem_u32(sm);
    int tid = threadIdx.x, lane = tid & 31, wid = tid >> 5;

    g1_issue(sb, tid, blockIdx.x << 7);   // prefetch first A tile

    {
        const uint4* s = (const uint4*)(g_w1t + (size_t)layer * 65536);
        #pragma unroll 2
        for (int i = tid; i < 4096; i += 512) {
            int r = i >> 4, c = i & 15;
            *(uint4*)(sm + G1_WH + r * STR1B + c * 16) = s[i];
            *(uint4*)(sm + G1_WL + r * STR1B + c * 16) = s[i + 4096];
        }
    }
    float* sAl = (float*)(sm + G1_ALPHA);
    float* sBe = (float*)(sm + G1_BETA);
    if (tid < 256) {
        int c = tid;
        float s = bn_g[c] * rsqrtf(bn_v[c] + BN_EPS);
        sAl[c] = s;
        sBe[c] = (bias[c] - bn_m[c]) * s + bn_b[c];
    }
    __syncthreads();

    int m0 = (wid >> 2) * 32, n0 = (wid & 3) * 64;
    uint32_t aoff = (uint32_t)((m0 + (lane & 15)) * STR1B + ((lane >> 4) << 4));
    uint32_t aAH = sb + G1_AH + aoff;
    uint32_t aAL = sb + G1_AL + aoff;
    uint32_t boff = (uint32_t)((n0 + ((lane >> 4) << 3) + (lane & 7)) * STR1B + (((lane >> 3) & 1) << 4));
    uint32_t aWH = sb + G1_WH + boff;
    uint32_t aWL = sb + G1_WL + boff;

    for (int tile = blockIdx.x; tile < NT; tile += gridDim.x) {
        int row0 = tile << 7;

        float acc[2][8][4];
        #pragma unroll
        for (int i = 0; i < 2; i++)
            #pragma unroll
            for (int j = 0; j < 8; j++)
                #pragma unroll
                for (int f = 0; f < 4; f++) acc[i][j][f] = 0.f;

        #pragma unroll
        for (int kp = 0; kp < 4; kp++) {
            cp_wait_dyn(6 - 2 * kp);
            __syncthreads();
            #pragma unroll
            for (int kq = 0; kq < 2; kq++) {
                int ks = kp * 2 + kq;
                uint32_t kb = ks << 5;
                uint32_t Ah[2][4], Alr[2][4], B[4][4];
                #pragma unroll
                for (int i = 0; i < 2; i++) {
                    LDSM_X4(Ah[i][0], Ah[i][1], Ah[i][2], Ah[i][3], aAH + i * (16 * STR1B) + kb);
                    LDSM_X4(Alr[i][0], Alr[i][1], Alr[i][2], Alr[i][3], aAL + i * (16 * STR1B) + kb);
                }
                #pragma unroll
                for (int j2 = 0; j2 < 4; j2++)
                    LDSM_X4(B[j2][0], B[j2][1], B[j2][2], B[j2][3], aWH + j2 * (16 * STR1B) + kb);
                #pragma unroll
                for (int i = 0; i < 2; i++)
                    #pragma unroll
                    for (int j = 0; j < 8; j++)
                        mma_bf16(acc[i][j][0], acc[i][j][1], acc[i][j][2], acc[i][j][3],
                                 Ah[i][0], Ah[i][1], Ah[i][2], Ah[i][3],
                                 B[j >> 1][(j & 1) * 2], B[j >> 1][(j & 1) * 2 + 1]);
                #pragma unroll
                for (int i = 0; i < 2; i++)
                    #pragma unroll
                    for (int j = 0; j < 8; j++)
                        mma_bf16(acc[i][j][0], acc[i][j][1], acc[i][j][2], acc[i][j][3],
                                 Alr[i][0], Alr[i][1], Alr[i][2], Alr[i][3],
                                 B[j >> 1][(j & 1) * 2], B[j >> 1][(j & 1) * 2 + 1]);
                #pragma unroll
                for (int j2 = 0; j2 < 4; j2++)
                    LDSM_X4(B[j2][0], B[j2][1], B[j2][2], B[j2][3], aWL + j2 * (16 * STR1B) + kb);
                #pragma unroll
                for (int i = 0; i < 2; i++)
                    #pragma unroll
                    for (int j = 0; j < 8; j++)
                        mma_bf16(acc[i][j][0], acc[i][j][1], acc[i][j][2], acc[i][j][3],
                                 Ah[i][0], Ah[i][1], Ah[i][2], Ah[i][3],
                                 B[j >> 1][(j & 1) * 2], B[j >> 1][(j & 1) * 2 + 1]);
            }
        }
        __syncthreads();                    // all warps done reading A smem
        g1_issue(sb, tid, (tile + gridDim.x) << 7);   // prefetch next tile

        // epilogue: BN + relu + split-bf16 store (overlaps with prefetch)
        int q = lane & 3;
        uint32_t* zh = (uint32_t*)g_z_hi;
        uint32_t* zl = (uint32_t*)g_z_lo;
        #pragma unroll
        for (int i = 0; i < 2; i++) {
            #pragma unroll
            for (int hf = 0; hf < 2; hf++) {
                int r = row0 + m0 + i * 16 + (lane >> 2) + hf * 8;
                if (r < N_NODES) {
                    size_t rb = (size_t)r * 128 + (n0 >> 1) + q;
                    #pragma unroll
                    for (int j = 0; j < 8; j++) {
                        int c = n0 + j * 8 + 2 * q;
                        float z0 = fmaxf(fmaf(acc[i][j][hf * 2],     sAl[c],     sBe[c]),     0.f);
                        float z1 = fmaxf(fmaf(acc[i][j][hf * 2 + 1], sAl[c + 1], sBe[c + 1]), 0.f);
                        __nv_bfloat16 h0, h1, l0, l1;
                        split_bf(z0, h0, l0); split_bf(z1, h1, l1);
                        zh[rb + j * 4] = pack_bf(h0, h1);
                        zl[rb + j * 4] = pack_bf(l0, l1);
                    }
                }
            }
        }
    }
}

// ---------------- GEMM2: h = BN_o(z @ W2 + b2)(+relu),  [N,256]x[256,128] --------
// 512 threads, 16 warps in 4x4 grid; warp tile 32(m) x 32(n)
__global__ void __launch_bounds__(512, 1) k_gemm2(
    int layer, const float* __restrict__ bias,
    const float* __restrict__ bn_g, const float* __restrict__ bn_b,
    const float* __restrict__ bn_m, const float* __restrict__ bn_v,
    float* __restrict__ out, int relu)
{
    extern __shared__ char sm[];
    uint32_t sb = smem_u32(sm);
    int tid = threadIdx.x, lane = tid & 31, wid = tid >> 5;

    g2_issue(sb, tid, blockIdx.x << 7, 0);

    {
        const uint4* s = (const uint4*)(g_w2t + (size_t)layer * 65536);
        #pragma unroll 2
        for (int i = tid; i < 4096; i += 512) {
            int r = i >> 5, c = i & 31;
            *(uint4*)(sm + G2_WH + r * STR2B + c * 16) = s[i];
            *(uint4*)(sm + G2_WL + r * STR2B + c * 16) = s[i + 4096];
        }
    }
    float* sAl = (float*)(sm + G2_ALPHA);
    float* sBe = (float*)(sm + G2_BETA);
    if (tid < 128) {
        int c = tid;
        float s = bn_g[c] * rsqrtf(bn_v[c] + BN_EPS);
        sAl[c] = s;
        sBe[c] = (bias[c] - bn_m[c]) * s + bn_b[c];
    }
    __syncthreads();

    int m0 = (wid >> 2) * 32, n0 = (wid & 3) * 32;
    uint32_t aoff = (uint32_t)((m0 + (lane & 15)) * STR1B + ((lane >> 4) << 4));
    uint32_t aZH = sb + G2_ZH + aoff;
    uint32_t aZL = sb + G2_ZL + aoff;
    uint32_t boff = (uint32_t)((n0 + ((lane >> 4) << 3) + (lane & 7)) * STR2B + (((lane >> 3) & 1) << 4));
    uint32_t aWH = sb + G2_WH + boff;
    uint32_t aWL = sb + G2_WL + boff;

    for (int tile = blockIdx.x; tile < NT; tile += gridDim.x) {
        int row0 = tile << 7;

        float acc[2][4][4];
        #pragma unroll
        for (int i = 0; i < 2; i++)
            #pragma unroll
            for (int j = 0; j < 4; j++)
                #pragma unroll
                for (int f = 0; f < 4; f++) acc[i][j][f] = 0.f;

        #pragma unroll 1
        for (int ch = 0; ch < 2; ch++) {
            uint32_t chb = (uint32_t)ch * 256;
            #pragma unroll
            for (int kp = 0; kp < 4; kp++) {
                cp_wait_dyn(6 - 2 * kp);
                __syncthreads();
                #pragma unroll
                for (int kq = 0; kq < 2; kq++) {
                    int ks = kp * 2 + kq;
                    uint32_t kb = ks << 5;
                    uint32_t Ah[2][4], Alr[2][4], B[2][4];
                    #pragma unroll
                    for (int i = 0; i < 2; i++) {
                        LDSM_X4(Ah[i][0], Ah[i][1], Ah[i][2], Ah[i][3], aZH + i * (16 * STR1B) + kb);
                        LDSM_X4(Alr[i][0], Alr[i][1], Alr[i][2], Alr[i][3], aZL + i * (16 * STR1B) + kb);
                    }
                    #pragma unroll
                    for (int j2 = 0; j2 < 2; j2++)
                        LDSM_X4(B[j2][0], B[j2][1], B[j2][2], B[j2][3],
                                aWH + j2 * (16 * STR2B) + chb + kb);
                    #pragma unroll
                    for (int i = 0; i < 2; i++)
                        #pragma unroll
                        for (int j = 0; j < 4; j++)
                            mma_bf16(acc[i][j][0], acc[i][j][1], acc[i][j][2], acc[i][j][3],
                                     Ah[i][0], Ah[i][1], Ah[i][2], Ah[i][3],
                                     B[j >> 1][(j & 1) * 2], B[j >> 1][(j & 1) * 2 + 1]);
                    #pragma unroll
                    for (int i = 0; i < 2; i++)
                        #pragma unroll
                        for (int j = 0; j < 4; j++)
                            mma_bf16(acc[i][j][0], acc[i][j][1], acc[i][j][2], acc[i][j][3],
                                     Alr[i][0], Alr[i][1], Alr[i][2], Alr[i][3],
                                     B[j >> 1][(j & 1) * 2], B[j >> 1][(j & 1) * 2 + 1]);
                    #pragma unroll
                    for (int j2 = 0; j2 < 2; j2++)
                        LDSM_X4(B[j2][0], B[j2][1], B[j2][2], B[j2][3],
                                aWL + j2 * (16 * STR2B) + chb + kb);
                    #pragma unroll
                    for (int i = 0; i < 2; i++)
                        #pragma unroll
                        for (int j = 0; j < 4; j++)
                            mma_bf16(acc[i][j][0], acc[i][j][1], acc[i][j][2], acc[i][j][3],
                                     Ah[i][0], Ah[i][1], Ah[i][2], Ah[i][3],
                                     B[j >> 1][(j & 1) * 2], B[j >> 1][(j & 1) * 2 + 1]);
                }
            }
            __syncthreads();                 // chunk consumed
            if (ch == 0)
                g2_issue(sb, tid, row0, 1);                       // chunk1 of this tile
            else
                g2_issue(sb, tid, (tile + gridDim.x) << 7, 0);    // chunk0 of next tile
        }

        // epilogue: BN (+relu), fp32 store (overlaps with next-tile prefetch)
        int q = lane & 3;
        #pragma unroll
        for (int i = 0; i < 2; i++) {
            #pragma unroll
            for (int hf = 0; hf < 2; hf++) {
                int r = row0 + m0 + i * 16 + (lane >> 2) + hf * 8;
                if (r < N_NODES) {
                    float* dst = out + (size_t)r * 128;
                    #pragma unroll
                    for (int j = 0; j < 4; j++) {
                        int c = n0 + j * 8 + 2 * q;
                        float z0 = fmaf(acc[i][j][hf * 2],     sAl[c],     sBe[c]);
                        float z1 = fmaf(acc[i][j][hf * 2 + 1], sAl[c + 1], sBe[c + 1]);
                        if (relu) { z0 = fmaxf(z0, 0.f); z1 = fmaxf(z1, 0.f); }
                        *(float2*)(dst + c) = make_float2(z0, z1);
                    }
                }
            }
        }
    }
}

// ---------------- launch ----------------------------------------------------------
extern "C" void kernel_launch(void* const* d_in, const int* in_sizes, int n_in,
                              void* d_out, int out_size) {
    const float* x     = (const float*)d_in[0];
    const int*   ei    = (const int*)d_in[1];
    const float* W1    = (const float*)d_in[2];
    const float* b1    = (const float*)d_in[3];
    const float* bn1_g = (const float*)d_in[4];
    const float* bn1_b = (const float*)d_in[5];
    const float* bn1_m = (const float*)d_in[6];
    const float* bn1_v = (const float*)d_in[7];
    const float* W2    = (const float*)d_in[8];
    const float* b2    = (const float*)d_in[9];
    const float* bno_g = (const float*)d_in[10];
    const float* bno_b = (const float*)d_in[11];
    const float* bno_m = (const float*)d_in[12];
    const float* bno_v = (const float*)d_in[13];
    float* out = (float*)d_out;

    cudaFuncSetAttribute(k_gemm1, cudaFuncAttributeMaxDynamicSharedMemorySize, SMEM1);
    cudaFuncSetAttribute(k_gemm2, cudaFuncAttributeMaxDynamicSharedMemorySize, SMEM2);

    const int* src = ei;
    const int* dst = ei + EDGES;

    k_wconv<<<(2 * LAYERS * 32768 + 255) / 256, 256>>>(W1, W2);
    k_zero<<<(N_NODES + 255) / 256, 256>>>();
    k_hist<<<(EDGES + 255) / 256, 256>>>(dst);
    k_scan_a<<<NSCAN, 1024>>>();
    k_scan_b<<<1, 32>>>();
    k_scan_c<<<NSCAN, 1024>>>();
    k_fill<<<(EDGES + 255) / 256, 256>>>(src, dst);

    const float* h = x;
    for (int l = 0; l < LAYERS; l++) {
        k_aggregate<<<(N_NODES * 32 + 255) / 256, 256>>>(h);
        k_gemm1<<<GRID_G, 512, SMEM1>>>(l, b1 + (size_t)l * 256,
                bn1_g + (size_t)l * 256, bn1_b + (size_t)l * 256,
                bn1_m + (size_t)l * 256, bn1_v + (size_t)l * 256);
        k_gemm2<<<GRID_G, 512, SMEM2>>>(l, b2 + (size_t)l * 128,
                bno_g + (size_t)l * 128, bno_b + (size_t)l * 128,
                bno_m + (size_t)l * 128, bno_v + (size_t)l * 128,
                out, (l != LAYERS - 1) ? 1 : 0);
        h = out;
    }
}